// round 11
// baseline (speedup 1.0000x reference)
#include <cuda_runtime.h>
#include <cstdint>

// YOLOv1 loss: preds [N,7,7,30] f32, labels [N,7,7,30] f32 -> scalar f32.
// R5's measured-best pipeline (2-stage cp.async, TILE=96, issue-before-wait)
// fused with in-kernel final reduction (no second launch, no graph gap).

#define TILE_CELLS 96
#define THREADS 96
#define FLOATS_PER_CELL 30
#define F4_PER_ARRAY 720            // 96*30/4
#define F4_PER_TILE 1440            // preds + labels
#define ITERS_PER_STAGE 15          // 1440 / 96 threads
#define MAX_BLOCKS 592              // 4 CTAs/SM * 148 SMs

__device__ float g_partials[MAX_BLOCKS];
__device__ unsigned int g_count;    // zero-init; atomicInc wraps to 0 -> replay-safe

__device__ __forceinline__ uint32_t smem_addr_u32(const void* p) {
    return (uint32_t)__cvta_generic_to_shared(p);
}

#define CP_ASYNC16(dst_u32, src_ptr) \
    asm volatile("cp.async.cg.shared.global [%0], [%1], 16;\n" :: "r"(dst_u32), "l"(src_ptr))
#define CP_COMMIT() asm volatile("cp.async.commit_group;\n" ::)
#define CP_WAIT1()  asm volatile("cp.async.wait_group 1;\n" ::)

__device__ __forceinline__ float iou_cxcywh(const float* a, const float* b) {
    float ax1 = a[0] - a[2] * 0.5f, ay1 = a[1] - a[3] * 0.5f;
    float ax2 = a[0] + a[2] * 0.5f, ay2 = a[1] + a[3] * 0.5f;
    float bx1 = b[0] - b[2] * 0.5f, by1 = b[1] - b[3] * 0.5f;
    float bx2 = b[0] + b[2] * 0.5f, by2 = b[1] + b[3] * 0.5f;
    float iw = fmaxf(fminf(ax2, bx2) - fmaxf(ax1, bx1), 0.0f);
    float ih = fmaxf(fminf(ay2, by2) - fmaxf(ay1, by1), 0.0f);
    float inter = iw * ih;
    float uni = a[2] * a[3] + b[2] * b[3] - inter;
    return inter / (uni + 1e-10f);
}

__global__ __launch_bounds__(THREADS) void yolo_loss_fused_kernel(
    const float4* __restrict__ preds4,
    const float4* __restrict__ labels4,
    float* __restrict__ out,
    int n_cells, int n_tiles, float inv_batch)
{
    __shared__ float4 buf[2][F4_PER_TILE];   // [stage][preds(720) | labels(720)]
    __shared__ float warp_s[THREADS / 32];
    __shared__ bool is_last;

    const int tid = threadIdx.x;

    // Issue one tile's loads into stage s (always commits a group, even if empty).
    auto issue_tile = [&](int t, int s) {
        if (t < n_tiles) {
            const int base = t * F4_PER_ARRAY;
            const int rem = n_cells - t * TILE_CELLS;
            const int vf4 = (rem >= TILE_CELLS) ? F4_PER_ARRAY
                                                : ((rem * FLOATS_PER_CELL + 3) >> 2);
#pragma unroll
            for (int k = 0; k < ITERS_PER_STAGE; ++k) {
                const int i = tid + k * THREADS;           // 0..1439
                const bool is_p = (i < F4_PER_ARRAY);
                const int j = is_p ? i : (i - F4_PER_ARRAY);
                const float4* src = (is_p ? preds4 : labels4) + base + j;
                const uint32_t dst = smem_addr_u32(&buf[s][i]);
                if (j < vf4) CP_ASYNC16(dst, src);
            }
        }
        CP_COMMIT();
    };

    float loss = 0.0f;
    int s = 0;

    // Prologue: prefetch first tile.
    issue_tile((int)blockIdx.x, 0);

    for (int t = blockIdx.x; t < n_tiles; t += gridDim.x) {
        // Keep the next tile's loads in flight while we compute this one.
        issue_tile(t + gridDim.x, s ^ 1);
        CP_WAIT1();                 // stage s complete (stage s^1 may still fly)
        __syncthreads();

        const int cell = t * TILE_CELLS + tid;
        if (cell < n_cells) {
            const float* bp = (const float*)buf[s];
            const float* p = bp + tid * FLOATS_PER_CELL;
            const float* l = bp + 4 * F4_PER_ARRAY + tid * FLOATS_PER_CELL;

            const float obj = (l[4] == 1.0f) ? 1.0f : 0.0f;

            const float i1 = iou_cxcywh(p, l);
            const float i2 = iou_cxcywh(p + 5, l);
            const bool b1 = i1 > i2;

            const float* pr = b1 ? p : (p + 5);
            const float* po = b1 ? (p + 5) : p;
            const float* lr = b1 ? l : (l + 5);   // label box duplicated in data
            const float iou_r = b1 ? i1 : i2;
            const float iou_o = b1 ? i2 : i1;

            float dx = pr[0] - lr[0];
            float dy = pr[1] - lr[1];
            float d_xy = dx * dx + dy * dy;

            float sw = sqrtf(pr[2]) - sqrtf(lr[2]);
            float sh = sqrtf(pr[3]) - sqrtf(lr[3]);
            float d_wh = sw * sw + sh * sh;

            float d_obj = pr[4] - iou_r;  d_obj *= d_obj;
            float d_no  = po[4] - iou_o;  d_no  *= d_no;
            float d_out = p[4] * p[4] + p[9] * p[9];

            float d_cls = 0.0f;
#pragma unroll
            for (int c = 10; c < 30; ++c) {
                float d = p[c] - l[c];
                d_cls = fmaf(d, d, d_cls);
            }

            loss += obj * (5.0f * d_xy + d_wh + d_obj + 0.5f * d_no + d_cls)
                  + (1.0f - obj) * 0.5f * d_out;
        }

        __syncthreads();            // everyone done with stage s before it is refilled
        s ^= 1;
    }

    // Per-block reduction -> partials slot.
#pragma unroll
    for (int o = 16; o > 0; o >>= 1)
        loss += __shfl_xor_sync(0xffffffffu, loss, o);
    if ((tid & 31) == 0) warp_s[tid >> 5] = loss;
    __syncthreads();

    if (tid == 0) {
        g_partials[blockIdx.x] = warp_s[0] + warp_s[1] + warp_s[2];
        __threadfence();
        unsigned int v = atomicInc(&g_count, gridDim.x - 1);  // wraps to 0 on last
        is_last = (v == gridDim.x - 1);
    }
    __syncthreads();

    // Last-arriving block folds all partials and writes the scalar output.
    if (is_last) {
        float tsum = 0.0f;
        for (int i = tid; i < (int)gridDim.x; i += THREADS)
            tsum += g_partials[i];
#pragma unroll
        for (int o = 16; o > 0; o >>= 1)
            tsum += __shfl_xor_sync(0xffffffffu, tsum, o);
        if ((tid & 31) == 0) warp_s[tid >> 5] = tsum;
        __syncthreads();
        if (tid == 0)
            out[0] = (warp_s[0] + warp_s[1] + warp_s[2]) * inv_batch;
    }
}

extern "C" void kernel_launch(void* const* d_in, const int* in_sizes, int n_in,
                              void* d_out, int out_size)
{
    const float4* preds4  = (const float4*)d_in[0];
    const float4* labels4 = (const float4*)d_in[1];
    float* out = (float*)d_out;

    const int total_floats = in_sizes[0];                    // N*7*7*30
    const int n_cells = total_floats / FLOATS_PER_CELL;      // N*49
    const int batch = n_cells / 49;                          // N
    const int n_tiles = (n_cells + TILE_CELLS - 1) / TILE_CELLS;

    const int n_blocks = (n_tiles < MAX_BLOCKS) ? n_tiles : MAX_BLOCKS;
    yolo_loss_fused_kernel<<<n_blocks, THREADS>>>(preds4, labels4, out,
                                                  n_cells, n_tiles,
                                                  1.0f / (float)batch);
}

// round 12
// speedup vs baseline: 1.0662x; 1.0662x over previous
#include <cuda_runtime.h>
#include <cstdint>

// YOLOv1 loss: preds [N,7,7,30] f32, labels [N,7,7,30] f32 -> scalar f32.
// Key insight (R11): kernel was MUFU-throughput-bound (6 MUFU/cell = 34us floor).
// Reduced to 3 MUFU/cell: shared reciprocal for both IoUs + (sqrt(a)-sqrt(b))^2
// = a+b-2*sqrt(ab). Memory pipeline: 2-stage cp.async, fused final reduction.

#define TILE_CELLS 96
#define THREADS 96
#define FLOATS_PER_CELL 30
#define F4_PER_ARRAY 720            // 96*30/4
#define F4_PER_TILE 1440            // preds + labels
#define ITERS_PER_STAGE 15          // 1440 / 96 threads
#define MAX_BLOCKS 592              // 4 CTAs/SM * 148 SMs

__device__ float g_partials[MAX_BLOCKS];
__device__ unsigned int g_count;    // zero-init; atomicInc wraps to 0 -> replay-safe

__device__ __forceinline__ uint32_t smem_addr_u32(const void* p) {
    return (uint32_t)__cvta_generic_to_shared(p);
}

#define CP_ASYNC16(dst_u32, src_ptr) \
    asm volatile("cp.async.cg.shared.global [%0], [%1], 16;\n" :: "r"(dst_u32), "l"(src_ptr))
#define CP_COMMIT() asm volatile("cp.async.commit_group;\n" ::)
#define CP_WAIT1()  asm volatile("cp.async.wait_group 1;\n" ::)

__device__ __forceinline__ float rcp_approx(float x) {
    float y; asm("rcp.approx.f32 %0, %1;" : "=f"(y) : "f"(x)); return y;
}
__device__ __forceinline__ float sqrt_approx(float x) {
    float y; asm("sqrt.approx.f32 %0, %1;" : "=f"(y) : "f"(x)); return y;
}

// inter & union of (cx,cy,w,h) boxes; no division here.
__device__ __forceinline__ void iou_parts(const float* a, const float* b,
                                          float& inter, float& uni) {
    float ax1 = a[0] - a[2] * 0.5f, ay1 = a[1] - a[3] * 0.5f;
    float ax2 = a[0] + a[2] * 0.5f, ay2 = a[1] + a[3] * 0.5f;
    float bx1 = b[0] - b[2] * 0.5f, by1 = b[1] - b[3] * 0.5f;
    float bx2 = b[0] + b[2] * 0.5f, by2 = b[1] + b[3] * 0.5f;
    float iw = fmaxf(fminf(ax2, bx2) - fmaxf(ax1, bx1), 0.0f);
    float ih = fmaxf(fminf(ay2, by2) - fmaxf(ay1, by1), 0.0f);
    inter = iw * ih;
    uni = a[2] * a[3] + b[2] * b[3] - inter + 1e-10f;
}

__global__ __launch_bounds__(THREADS) void yolo_loss_fused_kernel(
    const float4* __restrict__ preds4,
    const float4* __restrict__ labels4,
    float* __restrict__ out,
    int n_cells, int n_tiles, float inv_batch)
{
    __shared__ float4 buf[2][F4_PER_TILE];   // [stage][preds(720) | labels(720)]
    __shared__ float warp_s[THREADS / 32];
    __shared__ bool is_last;

    const int tid = threadIdx.x;

    auto issue_tile = [&](int t, int s) {
        if (t < n_tiles) {
            const int base = t * F4_PER_ARRAY;
            const int rem = n_cells - t * TILE_CELLS;
            const int vf4 = (rem >= TILE_CELLS) ? F4_PER_ARRAY
                                                : ((rem * FLOATS_PER_CELL + 3) >> 2);
#pragma unroll
            for (int k = 0; k < ITERS_PER_STAGE; ++k) {
                const int i = tid + k * THREADS;           // 0..1439
                const bool is_p = (i < F4_PER_ARRAY);
                const int j = is_p ? i : (i - F4_PER_ARRAY);
                const float4* src = (is_p ? preds4 : labels4) + base + j;
                const uint32_t dst = smem_addr_u32(&buf[s][i]);
                if (j < vf4) CP_ASYNC16(dst, src);
            }
        }
        CP_COMMIT();
    };

    float loss = 0.0f;
    int s = 0;

    issue_tile((int)blockIdx.x, 0);

    for (int t = blockIdx.x; t < n_tiles; t += gridDim.x) {
        issue_tile(t + gridDim.x, s ^ 1);   // next tile stays in flight
        CP_WAIT1();                          // stage s landed
        __syncthreads();

        const int cell = t * TILE_CELLS + tid;
        if (cell < n_cells) {
            const float* bp = (const float*)buf[s];
            const float* p = bp + tid * FLOATS_PER_CELL;
            const float* l = bp + 4 * F4_PER_ARRAY + tid * FLOATS_PER_CELL;

            const float obj = (l[4] == 1.0f) ? 1.0f : 0.0f;

            // Both IoUs with ONE reciprocal (MUFU #1):
            // i1 = n1/u1, i2 = n2/u2  ->  r = 1/(u1*u2); i1 = n1*u2*r; i2 = n2*u1*r.
            float n1, u1, n2, u2;
            iou_parts(p, l, n1, u1);
            iou_parts(p + 5, l, n2, u2);
            const float r = rcp_approx(u1 * u2);
            const float i1 = n1 * u2 * r;
            const float i2 = n2 * u1 * r;
            const bool b1 = i1 > i2;

            const float* pr = b1 ? p : (p + 5);
            const float* po = b1 ? (p + 5) : p;
            const float* lr = b1 ? l : (l + 5);   // label box duplicated in data
            const float iou_r = b1 ? i1 : i2;
            const float iou_o = b1 ? i2 : i1;

            float dx = pr[0] - lr[0];
            float dy = pr[1] - lr[1];
            float d_xy = dx * dx + dy * dy;

            // (sqrt(a)-sqrt(b))^2 = a + b - 2*sqrt(a*b): 2 MUFU instead of 4.
            const float pw = pr[2], ph = pr[3], lw = lr[2], lh = lr[3];
            float d_wh = (pw + lw - 2.0f * sqrt_approx(pw * lw))
                       + (ph + lh - 2.0f * sqrt_approx(ph * lh));

            float d_obj = pr[4] - iou_r;  d_obj *= d_obj;
            float d_no  = po[4] - iou_o;  d_no  *= d_no;
            float d_out = p[4] * p[4] + p[9] * p[9];

            float d_cls = 0.0f;
#pragma unroll
            for (int c = 10; c < 30; ++c) {
                float d = p[c] - l[c];
                d_cls = fmaf(d, d, d_cls);
            }

            loss += obj * (5.0f * d_xy + d_wh + d_obj + 0.5f * d_no + d_cls)
                  + (1.0f - obj) * 0.5f * d_out;
        }

        __syncthreads();            // everyone done with stage s before refill
        s ^= 1;
    }

    // Per-block reduction -> partials slot.
#pragma unroll
    for (int o = 16; o > 0; o >>= 1)
        loss += __shfl_xor_sync(0xffffffffu, loss, o);
    if ((tid & 31) == 0) warp_s[tid >> 5] = loss;
    __syncthreads();

    if (tid == 0) {
        g_partials[blockIdx.x] = warp_s[0] + warp_s[1] + warp_s[2];
        __threadfence();
        unsigned int v = atomicInc(&g_count, gridDim.x - 1);  // wraps to 0 on last
        is_last = (v == gridDim.x - 1);
    }
    __syncthreads();

    if (is_last) {
        float tsum = 0.0f;
        for (int i = tid; i < (int)gridDim.x; i += THREADS)
            tsum += g_partials[i];
#pragma unroll
        for (int o = 16; o > 0; o >>= 1)
            tsum += __shfl_xor_sync(0xffffffffu, tsum, o);
        if ((tid & 31) == 0) warp_s[tid >> 5] = tsum;
        __syncthreads();
        if (tid == 0)
            out[0] = (warp_s[0] + warp_s[1] + warp_s[2]) * inv_batch;
    }
}

extern "C" void kernel_launch(void* const* d_in, const int* in_sizes, int n_in,
                              void* d_out, int out_size)
{
    const float4* preds4  = (const float4*)d_in[0];
    const float4* labels4 = (const float4*)d_in[1];
    float* out = (float*)d_out;

    const int total_floats = in_sizes[0];                    // N*7*7*30
    const int n_cells = total_floats / FLOATS_PER_CELL;      // N*49
    const int batch = n_cells / 49;                          // N
    const int n_tiles = (n_cells + TILE_CELLS - 1) / TILE_CELLS;

    const int n_blocks = (n_tiles < MAX_BLOCKS) ? n_tiles : MAX_BLOCKS;
    yolo_loss_fused_kernel<<<n_blocks, THREADS>>>(preds4, labels4, out,
                                                  n_cells, n_tiles,
                                                  1.0f / (float)batch);
}